// round 15
// baseline (speedup 1.0000x reference)
#include <cuda_runtime.h>

// Problem constants
#define NN 512
#define KK 17
#define WW 48
#define HH 64
#define NK (NN * KK)                       // 8704
#define HMSZ (HH * WW)                     // 3072 floats
#define TOTAL ((double)NN * KK * HH * WW)  // 26738688

#define GRID 592                           // 4 blocks/SM * 148 SMs, single wave
#define NWARP 8                            // warps per block (256 threads)
#define GWARPS (GRID * NWARP)              // 4736 warps total
#define PF 6                               // stream pipeline depth (float4s/lane)

__device__ double g_acc;          // zero-init; reset by last block each run
__device__ unsigned int g_cnt;    // ditto

__global__ __launch_bounds__(256, 4) void loss_kernel(
    const float* __restrict__ pred,      // [N,K,2]
    const float* __restrict__ sigma,     // [N,K,2]
    const float* __restrict__ teacher,   // [N,K,H,W]
    const float* __restrict__ twgt,      // [N,K,1]
    float* __restrict__ out)             // [1]
{
    const int tid  = threadIdx.x;
    const int wid  = tid >> 5;
    const int lane = tid & 31;
    const int gw   = blockIdx.x * NWARP + wid;   // global warp id

    // Warp-private double-buffered tables: [0..47]=ex, [48..111]=ey
    __shared__ __align__(16) float tab[NWARP][2][128];

    const float2* __restrict__ pred2  = (const float2*)pred;
    const float2* __restrict__ sigma2 = (const float2*)sigma;

    float acc = 0.0f;

    // ---- Prime params for first heatmap ----
    float2 pr, sg;
    float  tv;
    if (gw < NK) {
        pr = pred2[gw];
        sg = sigma2[gw];
        tv = twgt[gw];
    } else {
        pr = make_float2(0.f, 0.f); sg = make_float2(1.f, 1.f); tv = 0.f;
    }

    int b = 0;
    for (int nk = gw; nk < NK; nk += GWARPS) {
        // ---- Prefetch NEXT heatmap's params (land during current stream) ----
        const int nk2 = nk + GWARPS;
        float2 prn, sgn;
        float  tvn;
        if (nk2 < NK) {
            prn = pred2[nk2];
            sgn = sigma2[nk2];
            tvn = twgt[nk2];
        } else {
            prn = make_float2(0.f, 0.f); sgn = make_float2(1.f, 1.f); tvn = 0.f;
        }

        const float4* __restrict__ tp =
            reinterpret_cast<const float4*>(teacher + (size_t)nk * HMSZ);

        // ---- Start the stream pipeline BEFORE the exp/table work ----
        float4 buf[PF];
#pragma unroll
        for (int j = 0; j < PF; j++)
            buf[j] = tp[lane + 32 * j];

        // ---- Tables for current heatmap (overlaps with loads in flight) ----
        const float mux = pr.x * (float)WW;
        const float muy = pr.y * (float)HH;
        const float sx  = sg.x;
        const float sy  = sg.y;
        const float m = ((mux - 3.0f * sx < (float)WW) &&
                         (muy - 3.0f * sy < (float)HH) &&
                         (mux + 3.0f * sx + 1.0f >= 0.0f) &&
                         (muy + 3.0f * sy + 1.0f >= 0.0f)) ? 1.0f : 0.0f;
        const float tw   = tv * m;
        const float coef = tw * tw;
        const float invx = 1.0f / (sx * sx + 1e-9f);
        const float invy = 1.0f / (sy * sy + 1e-9f);

        float* exb = tab[wid][b];
        float* eyb = tab[wid][b] + 48;
        {
            float d = (float)lane - mux;
            exb[lane] = __expf(-0.5f * d * d * invx);
            if (lane < WW - 32) {
                float d2 = (float)(lane + 32) - mux;
                exb[lane + 32] = __expf(-0.5f * d2 * d2 * invx);
            }
            float dy = (float)lane - muy;
            eyb[lane] = __expf(-0.5f * dy * dy * invy);
            float dy2 = (float)(lane + 32) - muy;
            eyb[lane + 32] = __expf(-0.5f * dy2 * dy2 * invy);
        }
        __syncwarp();   // tables visible; double-buffer bounds cross-iter slip

        const float4* __restrict__ ex4 = reinterpret_cast<const float4*>(exb);

        // ---- Software-pipelined stream: consume slot, reissue j+PF into it ----
        float wsum = 0.0f;
#pragma unroll
        for (int j = 0; j < 24; j++) {
            const float4 t = buf[j % PF];            // consume (reg copy)
            if (j + PF < 24)
                buf[j % PF] = tp[lane + 32 * (j + PF)];  // WAR reissue -> MLP~PF

            const int q = lane + 32 * j;             // quad index 0..767
            const int h = q / 12;                    // 12 quads per row (W=48)
            const int c = q % 12;
            const float4 e = ex4[c];                 // LDS.128
            const float  y = eyb[h];                 // LDS

            float d0 = e.x * y - t.x;
            float d1 = e.y * y - t.y;
            float d2 = e.z * y - t.z;
            float d3 = e.w * y - t.w;
            wsum += d0 * d0 + d1 * d1 + d2 * d2 + d3 * d3;
        }
        acc += wsum * coef;

        // ---- Shift param pipeline ----
        pr = prn; sg = sgn; tv = tvn;
        b ^= 1;
    }

    // ---- Block reduce (single __syncthreads in the kernel) ----
    __shared__ float s_warp[NWARP];
#pragma unroll
    for (int off = 16; off > 0; off >>= 1)
        acc += __shfl_down_sync(0xFFFFFFFFu, acc, off);
    if (lane == 0) s_warp[wid] = acc;
    __syncthreads();

    if (tid < NWARP) {
        float v = s_warp[tid];
#pragma unroll
        for (int off = NWARP / 2; off > 0; off >>= 1)
            v += __shfl_down_sync((1u << NWARP) - 1u, v, off);
        if (tid == 0) {
            atomicAdd(&g_acc, (double)v);
            __threadfence();
            unsigned int ticket = atomicAdd(&g_cnt, 1u);
            if (ticket == GRID - 1) {
                double total = atomicAdd(&g_acc, 0.0);   // coherent read
                out[0] = (float)(total / TOTAL);         // LOSS_WEIGHT = 1.0
                g_acc = 0.0;                             // reset for next replay
                g_cnt = 0u;
            }
        }
    }
}

extern "C" void kernel_launch(void* const* d_in, const int* in_sizes, int n_in,
                              void* d_out, int out_size) {
    const float* pred    = (const float*)d_in[0];
    const float* sigma   = (const float*)d_in[1];
    const float* teacher = (const float*)d_in[2];
    const float* twgt    = (const float*)d_in[3];
    float* out = (float*)d_out;

    loss_kernel<<<GRID, 256>>>(pred, sigma, teacher, twgt, out);
}

// round 16
// speedup vs baseline: 1.5970x; 1.5970x over previous
#include <cuda_runtime.h>

// Problem constants
#define NN 512
#define KK 17
#define WW 48
#define HH 64
#define NK (NN * KK)                       // 8704
#define HMSZ (HH * WW)                     // 3072 floats
#define TOTAL ((double)NN * KK * HH * WW)  // 26738688

#define GRID 592                           // 4 blocks/SM * 148 SMs, single wave
#define NWARP 8                            // warps per block (256 threads)
#define GWARPS (GRID * NWARP)              // 4736 warps total

__device__ double g_acc;          // zero-init; reset by last block each run
__device__ unsigned int g_cnt;    // ditto

__global__ __launch_bounds__(256, 4) void loss_kernel(
    const float* __restrict__ pred,      // [N,K,2]
    const float* __restrict__ sigma,     // [N,K,2]
    const float* __restrict__ teacher,   // [N,K,H,W]
    const float* __restrict__ twgt,      // [N,K,1]
    float* __restrict__ out)             // [1]
{
    const int tid  = threadIdx.x;
    const int wid  = tid >> 5;
    const int lane = tid & 31;
    // TRANSPOSED global warp id: every block gets the same mix of
    // 2-heatmap and 1-heatmap warps -> per-SM work is uniform.
    const int gw   = wid * GRID + blockIdx.x;

    // Warp-private double-buffered tables: [0..47]=ex, [48..111]=ey
    __shared__ __align__(16) float tab[NWARP][2][128];

    const float2* __restrict__ pred2  = (const float2*)pred;
    const float2* __restrict__ sigma2 = (const float2*)sigma;

    float acc = 0.0f;

    // ---- Prime params for first heatmap ----
    float2 pr, sg;
    float  tv;
    if (gw < NK) {
        pr = pred2[gw];
        sg = sigma2[gw];
        tv = twgt[gw];
    } else {
        pr = make_float2(0.f, 0.f); sg = make_float2(1.f, 1.f); tv = 0.f;
    }

    int b = 0;
    for (int nk = gw; nk < NK; nk += GWARPS) {
        // ---- Prefetch NEXT heatmap's params (land during current stream) ----
        const int nk2 = nk + GWARPS;
        float2 prn, sgn;
        float  tvn;
        if (nk2 < NK) {
            prn = pred2[nk2];
            sgn = sigma2[nk2];
            tvn = twgt[nk2];
        } else {
            prn = make_float2(0.f, 0.f); sgn = make_float2(1.f, 1.f); tvn = 0.f;
        }

        // ---- Tables for current heatmap (params already in registers) ----
        const float mux = pr.x * (float)WW;
        const float muy = pr.y * (float)HH;
        const float sx  = sg.x;
        const float sy  = sg.y;
        const float m = ((mux - 3.0f * sx < (float)WW) &&
                         (muy - 3.0f * sy < (float)HH) &&
                         (mux + 3.0f * sx + 1.0f >= 0.0f) &&
                         (muy + 3.0f * sy + 1.0f >= 0.0f)) ? 1.0f : 0.0f;
        const float tw   = tv * m;
        const float coef = tw * tw;
        const float invx = 1.0f / (sx * sx + 1e-9f);
        const float invy = 1.0f / (sy * sy + 1e-9f);

        float* exb = tab[wid][b];
        float* eyb = tab[wid][b] + 48;
        {
            float d = (float)lane - mux;
            exb[lane] = __expf(-0.5f * d * d * invx);
            if (lane < WW - 32) {
                float d2 = (float)(lane + 32) - mux;
                exb[lane + 32] = __expf(-0.5f * d2 * d2 * invx);
            }
            float dy = (float)lane - muy;
            eyb[lane] = __expf(-0.5f * dy * dy * invy);
            float dy2 = (float)(lane + 32) - muy;
            eyb[lane + 32] = __expf(-0.5f * dy2 * dy2 * invy);
        }
        __syncwarp();   // tables visible; double-buffer bounds cross-iter slip

        // ---- Stream this warp's heatmap: 24 float4 per lane ----
        const float4* __restrict__ tp  = reinterpret_cast<const float4*>(teacher + (size_t)nk * HMSZ);
        const float4* __restrict__ ex4 = reinterpret_cast<const float4*>(exb);

        float wsum = 0.0f;
#pragma unroll 6
        for (int k = 0; k < 24; k++) {
            const int q = lane + 32 * k;   // quad index 0..767
            const float4 t = tp[q];
            const int h = q / 12;          // 12 quads per row (W=48)
            const int c = q % 12;
            const float4 e = ex4[c];       // LDS.128
            const float  y = eyb[h];       // LDS

            float d0 = e.x * y - t.x;
            float d1 = e.y * y - t.y;
            float d2 = e.z * y - t.z;
            float d3 = e.w * y - t.w;
            wsum += d0 * d0 + d1 * d1 + d2 * d2 + d3 * d3;
        }
        acc += wsum * coef;

        // ---- Shift param pipeline ----
        pr = prn; sg = sgn; tv = tvn;
        b ^= 1;
    }

    // ---- Block reduce (single __syncthreads in the kernel) ----
    __shared__ float s_warp[NWARP];
#pragma unroll
    for (int off = 16; off > 0; off >>= 1)
        acc += __shfl_down_sync(0xFFFFFFFFu, acc, off);
    if (lane == 0) s_warp[wid] = acc;
    __syncthreads();

    if (tid < NWARP) {
        float v = s_warp[tid];
#pragma unroll
        for (int off = NWARP / 2; off > 0; off >>= 1)
            v += __shfl_down_sync((1u << NWARP) - 1u, v, off);
        if (tid == 0) {
            atomicAdd(&g_acc, (double)v);
            __threadfence();
            unsigned int ticket = atomicAdd(&g_cnt, 1u);
            if (ticket == GRID - 1) {
                double total = atomicAdd(&g_acc, 0.0);   // coherent read
                out[0] = (float)(total / TOTAL);         // LOSS_WEIGHT = 1.0
                g_acc = 0.0;                             // reset for next replay
                g_cnt = 0u;
            }
        }
    }
}

extern "C" void kernel_launch(void* const* d_in, const int* in_sizes, int n_in,
                              void* d_out, int out_size) {
    const float* pred    = (const float*)d_in[0];
    const float* sigma   = (const float*)d_in[1];
    const float* teacher = (const float*)d_in[2];
    const float* twgt    = (const float*)d_in[3];
    float* out = (float*)d_out;

    loss_kernel<<<GRID, 256>>>(pred, sigma, teacher, twgt, out);
}